// round 7
// baseline (speedup 1.0000x reference)
#include <cuda_runtime.h>
#include <math.h>

#define B_ 64
#define T_ 1024
#define E_ 512
#define H_ 256
#define M_ (B_*T_)          // 65536

#define HB 288              // padded h buffer: pos(k) = k + (k>>5)*4, max 283

// ---------------- scratch (device globals; no allocation allowed) ----------------
__device__ float g_xp[(size_t)2*T_*B_*H_];     // per-layer projections [2][T][B][H]
__device__ float g_x1[(size_t)M_*512];         // layer0 output concat  [M,512]
__device__ float g_x2[(size_t)M_*512];         // layer1 output concat  [M,512]
__device__ float g_xph[(size_t)T_*B_*16];      // head projections      [T][B][16] (13 used)

// ---------------- packed f32x2 FMA (Blackwell) ----------------
__device__ __forceinline__ void ffma2(float2 &acc, float2 a, float2 b) {
    asm("fma.rn.f32x2 %0, %1, %2, %0;"
        : "+l"(reinterpret_cast<unsigned long long&>(acc))
        : "l"(reinterpret_cast<unsigned long long&>(a)),
          "l"(reinterpret_cast<unsigned long long&>(b)));
}

// fast tanh: exp-based, ~1e-6 relative error
__device__ __forceinline__ float ftanh(float x) {
    float ax = fabsf(x);
    float e  = __expf(-2.f * ax);
    float r  = __fdividef(1.f - e, 1.f + e);
    return copysignf(r, x);
}

// ---------------- 1) input projection GEMM (k-tile 16, double-buffered) -------
// A row m: which_A==0 -> emb[tokens[m]] (fused gather), else g_x1 row m.
// C[m,n] = sum_k A[m,k]*W[n,k] + bih[n] + bhh[n]  -> g_xp[d][t][b][h]
__global__ __launch_bounds__(256, 2) void gemm_xp_kernel(
    int which_A,
    const int*   __restrict__ tokens,  // [M]
    const float* __restrict__ emb,     // [V,512]
    const float* __restrict__ W,       // [512,512]
    const float* __restrict__ bih,     // [512]
    const float* __restrict__ bhh)     // [512]
{
    __shared__ float As[2][16][128];
    __shared__ float Bs[2][16][128];

    int tid = threadIdx.x;
    int m0 = blockIdx.x * 128;
    int n0 = blockIdx.y * 128;
    int lr = tid >> 1, lh = tid & 1;          // row 0..127, col-half 0/1

    const float* Ap;
    if (which_A) {
        Ap = g_x1 + (size_t)(m0 + lr) * 512 + lh * 8;
    } else {
        int tok = __ldg(&tokens[m0 + lr]);
        Ap = emb + (size_t)tok * 512 + lh * 8;
    }
    const float* Wp = W + (size_t)(n0 + lr) * 512 + lh * 8;
    int ty = tid >> 4, tx = tid & 15;

    float2 acc[8][4];
#pragma unroll
    for (int i = 0; i < 8; i++)
#pragma unroll
        for (int j = 0; j < 4; j++) acc[i][j] = make_float2(0.f, 0.f);

    // preload tile 0
    {
        float4 a0 = *(const float4*)(Ap);
        float4 a1 = *(const float4*)(Ap + 4);
        float4 w0 = *(const float4*)(Wp);
        float4 w1 = *(const float4*)(Wp + 4);
        As[0][lh*8+0][lr]=a0.x; As[0][lh*8+1][lr]=a0.y; As[0][lh*8+2][lr]=a0.z; As[0][lh*8+3][lr]=a0.w;
        As[0][lh*8+4][lr]=a1.x; As[0][lh*8+5][lr]=a1.y; As[0][lh*8+6][lr]=a1.z; As[0][lh*8+7][lr]=a1.w;
        Bs[0][lh*8+0][lr]=w0.x; Bs[0][lh*8+1][lr]=w0.y; Bs[0][lh*8+2][lr]=w0.z; Bs[0][lh*8+3][lr]=w0.w;
        Bs[0][lh*8+4][lr]=w1.x; Bs[0][lh*8+5][lr]=w1.y; Bs[0][lh*8+6][lr]=w1.z; Bs[0][lh*8+7][lr]=w1.w;
    }
    __syncthreads();

    for (int k0 = 0; k0 < 512; k0 += 16) {
        int p = (k0 >> 4) & 1;
        float4 a0, a1, w0, w1;
        bool more = (k0 + 16 < 512);
        if (more) {
            a0 = *(const float4*)(Ap + k0 + 16);
            a1 = *(const float4*)(Ap + k0 + 20);
            w0 = *(const float4*)(Wp + k0 + 16);
            w1 = *(const float4*)(Wp + k0 + 20);
        }
#pragma unroll
        for (int kk = 0; kk < 16; kk++) {
            float a[8];
            *(float4*)&a[0] = *(const float4*)&As[p][kk][ty*8];
            *(float4*)&a[4] = *(const float4*)&As[p][kk][ty*8+4];
            float4 b0 = *(const float4*)&Bs[p][kk][tx*8];
            float4 b1 = *(const float4*)&Bs[p][kk][tx*8+4];
            float2 bp[4] = { make_float2(b0.x,b0.y), make_float2(b0.z,b0.w),
                             make_float2(b1.x,b1.y), make_float2(b1.z,b1.w) };
#pragma unroll
            for (int i = 0; i < 8; i++) {
                float2 ap = make_float2(a[i], a[i]);
#pragma unroll
                for (int j = 0; j < 4; j++) ffma2(acc[i][j], ap, bp[j]);
            }
        }
        if (more) {
            int q = p ^ 1;
            As[q][lh*8+0][lr]=a0.x; As[q][lh*8+1][lr]=a0.y; As[q][lh*8+2][lr]=a0.z; As[q][lh*8+3][lr]=a0.w;
            As[q][lh*8+4][lr]=a1.x; As[q][lh*8+5][lr]=a1.y; As[q][lh*8+6][lr]=a1.z; As[q][lh*8+7][lr]=a1.w;
            Bs[q][lh*8+0][lr]=w0.x; Bs[q][lh*8+1][lr]=w0.y; Bs[q][lh*8+2][lr]=w0.z; Bs[q][lh*8+3][lr]=w0.w;
            Bs[q][lh*8+4][lr]=w1.x; Bs[q][lh*8+5][lr]=w1.y; Bs[q][lh*8+6][lr]=w1.z; Bs[q][lh*8+7][lr]=w1.w;
        }
        __syncthreads();
    }

#pragma unroll
    for (int i = 0; i < 8; i++) {
        int m = m0 + ty*8 + i;
        int bb = m >> 10, t = m & 1023;
#pragma unroll
        for (int p = 0; p < 2; p++) {
            int n = n0 + tx*8 + p*4;
            int d = n >> 8, h = n & 255;
            float4 v;
            v.x = acc[i][p*2  ].x + bih[n  ] + bhh[n  ];
            v.y = acc[i][p*2  ].y + bih[n+1] + bhh[n+1];
            v.z = acc[i][p*2+1].x + bih[n+2] + bhh[n+2];
            v.w = acc[i][p*2+1].y + bih[n+3] + bhh[n+3];
            *(float4*)&g_xp[(((size_t)d*T_ + t)*B_ + bb)*H_ + h] = v;
        }
    }
}

// ---------------- 2) bidirectional RNN recurrence (distinct-h layout) ---------
// One CTA per (batch, dir). 512 threads = 16 warps.
// Thread: warp w, lane: s = lane>>2 (k-slice of 32), chq = lane&3.
// Computes partial dots for 4 channels ch0..ch0+3 (ch0 = w*16 + chq*4)
// over k in [s*32, s*32+32). W: k-rel 0..23 in regs (48 f32x2), 24..31 in smem.
// Butterfly-reduce over the 8 k-slice lanes; lane s==0 finalizes (x + tanh),
// writes h float4 + output float4. Double-buffered h, ONE barrier per step.
__global__ __launch_bounds__(512, 1) void rnn_layer_kernel(
    const float* __restrict__ whh,     // [2][H][H] (this layer)
    int which_out)                     // 0 -> g_x1, 1 -> g_x2
{
    extern __shared__ float sm[];
    float4* Wsm4 = (float4*)sm;                // [8][512] float4 = 64 KB
    float*  hbuf = sm + 8 * 512 * 4;           // [2][HB]
    float*  xnext = which_out ? g_x2 : g_x1;

    int tid  = threadIdx.x;
    int w    = tid >> 5, lane = tid & 31;
    int s    = lane >> 2;          // k-slice 0..7
    int chq  = lane & 3;
    int ch0  = w * 16 + chq * 4;   // 4 consecutive channels
    int d = blockIdx.x & 1;
    int b = blockIdx.x >> 1;
    const float* Wd = whh + (size_t)d * H_ * H_;

    // register weights: W[ch0+c][s*32 + 0..23]  (12 f32x2 per channel)
    float2 wreg[4][12];
#pragma unroll
    for (int c = 0; c < 4; c++) {
        const float2* row = (const float2*)(Wd + (size_t)(ch0 + c) * H_ + s * 32);
#pragma unroll
        for (int q = 0; q < 12; q++) wreg[c][q] = row[q];
    }
    // smem weights: W[ch0+c][s*32 + 24 + 4q], q=0,1
#pragma unroll
    for (int c = 0; c < 4; c++)
#pragma unroll
        for (int q = 0; q < 2; q++)
            Wsm4[(c*2 + q) * 512 + tid] =
                *(const float4*)(Wd + (size_t)(ch0 + c) * H_ + s * 32 + 24 + 4*q);

    for (int idx = tid; idx < 2 * HB; idx += 512) hbuf[idx] = 0.f;
    __syncthreads();

    const float* xpd = g_xp + (size_t)d * T_ * B_ * H_;
    float* outbase = xnext + (size_t)b * T_ * 512 + d * H_ + ch0;

    int t = d ? (T_ - 1) : 0;
    int step = d ? -1 : 1;

    float4 xv = make_float4(0.f,0.f,0.f,0.f);
    if (lane < 4)
        xv = *(const float4*)&xpd[((size_t)t * B_ + b) * H_ + ch0];

    int rb = 0;
    for (int it = 0; it < T_; ++it) {
        float4 xnv = make_float4(0.f,0.f,0.f,0.f);
        if (lane < 4 && it + 1 < T_)
            xnv = *(const float4*)&xpd[((size_t)(t + step) * B_ + b) * H_ + ch0];

        // h slice: pos(k)=k+(k>>5)*4 -> slice s starts at word 36*s, 8 float4
        const float4* hsl = (const float4*)(hbuf + rb * HB + s * 36);

        float2 a0 = make_float2(0.f,0.f), a1 = a0, a2 = a0, a3 = a0;
#pragma unroll
        for (int i = 0; i < 6; i++) {               // k-rel 0..23 (register W)
            float4 hv = hsl[i];
            float2 hlo = make_float2(hv.x, hv.y);
            float2 hhi = make_float2(hv.z, hv.w);
            ffma2(a0, hlo, wreg[0][2*i]); ffma2(a0, hhi, wreg[0][2*i+1]);
            ffma2(a1, hlo, wreg[1][2*i]); ffma2(a1, hhi, wreg[1][2*i+1]);
            ffma2(a2, hlo, wreg[2][2*i]); ffma2(a2, hhi, wreg[2][2*i+1]);
            ffma2(a3, hlo, wreg[3][2*i]); ffma2(a3, hhi, wreg[3][2*i+1]);
        }
        {                                            // k-rel 24..31 (smem W)
            float4 h6 = hsl[6], h7 = hsl[7];
            float2 h6lo = make_float2(h6.x,h6.y), h6hi = make_float2(h6.z,h6.w);
            float2 h7lo = make_float2(h7.x,h7.y), h7hi = make_float2(h7.z,h7.w);
            {
                float4 wa = Wsm4[0*512+tid], wb2 = Wsm4[1*512+tid];
                ffma2(a0, h6lo, make_float2(wa.x,wa.y));  ffma2(a0, h6hi, make_float2(wa.z,wa.w));
                ffma2(a0, h7lo, make_float2(wb2.x,wb2.y));ffma2(a0, h7hi, make_float2(wb2.z,wb2.w));
            }
            {
                float4 wa = Wsm4[2*512+tid], wb2 = Wsm4[3*512+tid];
                ffma2(a1, h6lo, make_float2(wa.x,wa.y));  ffma2(a1, h6hi, make_float2(wa.z,wa.w));
                ffma2(a1, h7lo, make_float2(wb2.x,wb2.y));ffma2(a1, h7hi, make_float2(wb2.z,wb2.w));
            }
            {
                float4 wa = Wsm4[4*512+tid], wb2 = Wsm4[5*512+tid];
                ffma2(a2, h6lo, make_float2(wa.x,wa.y));  ffma2(a2, h6hi, make_float2(wa.z,wa.w));
                ffma2(a2, h7lo, make_float2(wb2.x,wb2.y));ffma2(a2, h7hi, make_float2(wb2.z,wb2.w));
            }
            {
                float4 wa = Wsm4[6*512+tid], wb2 = Wsm4[7*512+tid];
                ffma2(a3, h6lo, make_float2(wa.x,wa.y));  ffma2(a3, h6hi, make_float2(wa.z,wa.w));
                ffma2(a3, h7lo, make_float2(wb2.x,wb2.y));ffma2(a3, h7hi, make_float2(wb2.z,wb2.w));
            }
        }
        float s0 = a0.x + a0.y, s1 = a1.x + a1.y;
        float s2 = a2.x + a2.y, s3 = a3.x + a3.y;
#pragma unroll
        for (int off = 4; off <= 16; off <<= 1) {   // reduce over 8 k-slices
            s0 += __shfl_xor_sync(0xffffffffu, s0, off);
            s1 += __shfl_xor_sync(0xffffffffu, s1, off);
            s2 += __shfl_xor_sync(0xffffffffu, s2, off);
            s3 += __shfl_xor_sync(0xffffffffu, s3, off);
        }

        int wb = rb ^ 1;
        if (lane < 4) {                             // s==0 lanes finalize
            float4 hn;
            hn.x = ftanh(s0 + xv.x);
            hn.y = ftanh(s1 + xv.y);
            hn.z = ftanh(s2 + xv.z);
            hn.w = ftanh(s3 + xv.w);
            *(float4*)&hbuf[wb * HB + ch0 + ((ch0 >> 5) << 2)] = hn;
            *(float4*)&outbase[(size_t)t * 512] = hn;
        }
        __syncthreads();
        xv = xnv;
        t += step;
        rb = wb;
    }
}

// ---------------- 3) head projections: relu(x2) @ [13x512]^T + biases ----------------
__global__ __launch_bounds__(256) void head_xp_kernel(
    const float* __restrict__ wi, const float* __restrict__ bi_ih, const float* __restrict__ bi_hh,
    const float* __restrict__ wf, const float* __restrict__ bf_ih, const float* __restrict__ bf_hh,
    const float* __restrict__ wc, const float* __restrict__ bc_ih, const float* __restrict__ bc_hh)
{
    __shared__ float Ws[13 * 512];
    __shared__ float bs[13];
    int tid = threadIdx.x;
    for (int idx = tid; idx < 13 * 512; idx += 256) {
        int n = idx / 512, k = idx % 512;
        float w;
        if (n < 3)      w = wi[n*512 + k];
        else if (n < 8) w = wf[(n-3)*512 + k];
        else            w = wc[(n-8)*512 + k];
        Ws[idx] = w;
    }
    if (tid < 13) {
        float bv;
        if (tid < 3)      bv = bi_ih[tid]   + bi_hh[tid];
        else if (tid < 8) bv = bf_ih[tid-3] + bf_hh[tid-3];
        else              bv = bc_ih[tid-8] + bc_hh[tid-8];
        bs[tid] = bv;
    }
    __syncthreads();

    int w = tid >> 5, lane = tid & 31;
    int m = blockIdx.x * 8 + w;
    const float* xr = g_x2 + (size_t)m * 512;

    float acc[13];
#pragma unroll
    for (int n = 0; n < 13; n++) acc[n] = 0.f;

    for (int i = 0; i < 16; i++) {
        int k = i * 32 + lane;
        float xv = xr[k];
        xv = xv > 0.f ? xv : 0.f;
#pragma unroll
        for (int n = 0; n < 13; n++) acc[n] += xv * Ws[n*512 + k];
    }
#pragma unroll
    for (int n = 0; n < 13; n++) {
#pragma unroll
        for (int off = 16; off; off >>= 1)
            acc[n] += __shfl_xor_sync(0xffffffff, acc[n], off);
    }
    if (lane == 0) {
        int bb = m >> 10, t = m & 1023;
        float* o = g_xph + ((size_t)t * B_ + bb) * 16;
#pragma unroll
        for (int n = 0; n < 13; n++) o[n] = acc[n] + bs[n];
    }
}

// ---------------- 4) head recurrences (3 tiny forward scans) ----------------
__global__ void head_rnn_kernel(
    const float* __restrict__ wi_hh,
    const float* __restrict__ wf_hh,
    const float* __restrict__ wc_hh,
    float* __restrict__ out)
{
    int hid = blockIdx.x % 3;
    int b   = blockIdx.x / 3;
    int lane = threadIdx.x;
    int C, off;
    size_t outoff;
    const float* Whh;
    if (hid == 0)      { C = 3; off = 0; outoff = 0;                         Whh = wi_hh; }
    else if (hid == 1) { C = 5; off = 3; outoff = (size_t)B_*T_*3;           Whh = wf_hh; }
    else               { C = 5; off = 8; outoff = (size_t)B_*T_*3 + (size_t)B_*T_*5; Whh = wc_hh; }

    float w[5] = {0,0,0,0,0};
    if (lane < C)
        for (int k = 0; k < C; k++) w[k] = Whh[lane*C + k];

    float h = 0.f;
    float* ob = out + outoff + (size_t)b * T_ * C;
    float xv = (lane < C) ? g_xph[((size_t)0 * B_ + b) * 16 + off + lane] : 0.f;
    for (int t = 0; t < T_; t++) {
        float xn = 0.f;
        if (t + 1 < T_ && lane < C)
            xn = g_xph[((size_t)(t+1) * B_ + b) * 16 + off + lane];
        float h0 = __shfl_sync(0xffffffff, h, 0);
        float h1 = __shfl_sync(0xffffffff, h, 1);
        float h2 = __shfl_sync(0xffffffff, h, 2);
        float h3 = __shfl_sync(0xffffffff, h, 3);
        float h4 = __shfl_sync(0xffffffff, h, 4);
        float acc = xv + h0*w[0] + h1*w[1] + h2*w[2] + h3*w[3] + h4*w[4];
        h = ftanh(acc);
        if (lane < C) ob[(size_t)t * C + lane] = h;
        xv = xn;
    }
}

// ---------------- launch ----------------
extern "C" void kernel_launch(void* const* d_in, const int* in_sizes, int n_in,
                              void* d_out, int out_size) {
    const int*   tokens = (const int*)  d_in[0];
    const float* emb    = (const float*)d_in[1];
    const float* w_ih   = (const float*)d_in[2];   // [2][2][256][512]
    const float* w_hh   = (const float*)d_in[3];   // [2][2][256][256]
    const float* b_ih   = (const float*)d_in[4];   // [2][2][256]
    const float* b_hh   = (const float*)d_in[5];
    const float* iw_ih  = (const float*)d_in[6];
    const float* iw_hh  = (const float*)d_in[7];
    const float* ib_ih  = (const float*)d_in[8];
    const float* ib_hh  = (const float*)d_in[9];
    const float* fw_ih  = (const float*)d_in[10];
    const float* fw_hh  = (const float*)d_in[11];
    const float* fb_ih  = (const float*)d_in[12];
    const float* fb_hh  = (const float*)d_in[13];
    const float* cw_ih  = (const float*)d_in[14];
    const float* cw_hh  = (const float*)d_in[15];
    const float* cb_ih  = (const float*)d_in[16];
    const float* cb_hh  = (const float*)d_in[17];
    float* out = (float*)d_out;

    const int rnn_smem = (8 * 512 * 4 + 2 * HB) * 4;   // 64 KB W + h bufs
    cudaFuncSetAttribute(rnn_layer_kernel,
                         cudaFuncAttributeMaxDynamicSharedMemorySize, rnn_smem);

    // layer 0: projection (fused embedding gather) + scan
    gemm_xp_kernel<<<dim3(M_/128, 512/128), 256>>>(0, tokens, emb,
                                                   w_ih, b_ih, b_hh);
    rnn_layer_kernel<<<B_ * 2, 512, rnn_smem>>>(w_hh, 0);

    // layer 1: projection + scan
    gemm_xp_kernel<<<dim3(M_/128, 512/128), 256>>>(1, tokens, emb,
                                                   w_ih + 2*H_*E_,
                                                   b_ih + 2*H_, b_hh + 2*H_);
    rnn_layer_kernel<<<B_ * 2, 512, rnn_smem>>>(w_hh + 2*H_*H_, 1);

    // head projections (with ReLU on the fly)
    head_xp_kernel<<<M_/8, 256>>>(iw_ih, ib_ih, ib_hh,
                                  fw_ih, fb_ih, fb_hh,
                                  cw_ih, cb_ih, cb_hh);

    // head scans -> final output
    head_rnn_kernel<<<B_ * 3, 32>>>(iw_hh, fw_hh, cw_hh, out);
}

// round 10
// speedup vs baseline: 1.0533x; 1.0533x over previous
#include <cuda_runtime.h>
#include <math.h>

#define B_ 64
#define T_ 1024
#define E_ 512
#define H_ 256
#define M_ (B_*T_)          // 65536

// RNN: 512 threads, thread pair (2j, 2j+1) computes channel j.
// Each thread covers 128 of the 256 h-elements: 96 in registers + 32 in smem.
#define WREG2 48            // float2 weights in registers per thread
#define WSH4  8             // float4 weights in shared per thread
#define HSTRIDE 132         // padded half-stride (132 % 32 == 4 -> bank shift)
#define HBUF   264          // one h buffer (2 halves)

// ---------------- scratch (device globals; no allocation allowed) ----------------
__device__ float g_xp[(size_t)2*T_*B_*H_];     // per-layer projections [2][T][B][H]
__device__ float g_x1[(size_t)M_*512];         // layer0 output concat  [M,512]
__device__ float g_x2[(size_t)M_*512];         // layer1 output concat  [M,512]
__device__ float g_xph[(size_t)T_*B_*16];      // head projections      [T][B][16] (13 used)

// ---------------- packed f32x2 FMA (Blackwell) ----------------
__device__ __forceinline__ void ffma2(float2 &acc, float2 a, float2 b) {
    asm("fma.rn.f32x2 %0, %1, %2, %0;"
        : "+l"(reinterpret_cast<unsigned long long&>(acc))
        : "l"(reinterpret_cast<unsigned long long&>(a)),
          "l"(reinterpret_cast<unsigned long long&>(b)));
}

// fast tanh: exp-based, ~1e-6 relative error
__device__ __forceinline__ float ftanh(float x) {
    float ax = fabsf(x);
    float e  = __expf(-2.f * ax);
    float r  = __fdividef(1.f - e, 1.f + e);
    return copysignf(r, x);
}

// ---------------- 1) input projection GEMM (k-tile 16, double-buffered) -------
// A row m: which_A==0 -> emb[tokens[m]] (fused gather), else g_x1 row m.
// C[m,n] = sum_k A[m,k]*W[n,k] + bih[n] + bhh[n]  -> g_xp[d][t][b][h]
// Loader decomposition: lr = tid&127 (row), lh = tid>>7 (col-half) so each
// warp's STS hits 32 consecutive words of one smem row -> conflict-free.
__global__ __launch_bounds__(256, 2) void gemm_xp_kernel(
    int which_A,
    const int*   __restrict__ tokens,  // [M]
    const float* __restrict__ emb,     // [V,512]
    const float* __restrict__ W,       // [512,512]
    const float* __restrict__ bih,     // [512]
    const float* __restrict__ bhh)     // [512]
{
    __shared__ float As[2][16][128];
    __shared__ float Bs[2][16][128];

    int tid = threadIdx.x;
    int m0 = blockIdx.x * 128;
    int n0 = blockIdx.y * 128;
    int lr = tid & 127, lh = tid >> 7;        // row 0..127, col-half 0/1

    const float* Ap;
    if (which_A) {
        Ap = g_x1 + (size_t)(m0 + lr) * 512 + lh * 8;
    } else {
        int tok = __ldg(&tokens[m0 + lr]);
        Ap = emb + (size_t)tok * 512 + lh * 8;
    }
    const float* Wp = W + (size_t)(n0 + lr) * 512 + lh * 8;
    int ty = tid >> 4, tx = tid & 15;

    float2 acc[8][4];
#pragma unroll
    for (int i = 0; i < 8; i++)
#pragma unroll
        for (int j = 0; j < 4; j++) acc[i][j] = make_float2(0.f, 0.f);

    // preload tile 0
    {
        float4 a0 = *(const float4*)(Ap);
        float4 a1 = *(const float4*)(Ap + 4);
        float4 w0 = *(const float4*)(Wp);
        float4 w1 = *(const float4*)(Wp + 4);
        As[0][lh*8+0][lr]=a0.x; As[0][lh*8+1][lr]=a0.y; As[0][lh*8+2][lr]=a0.z; As[0][lh*8+3][lr]=a0.w;
        As[0][lh*8+4][lr]=a1.x; As[0][lh*8+5][lr]=a1.y; As[0][lh*8+6][lr]=a1.z; As[0][lh*8+7][lr]=a1.w;
        Bs[0][lh*8+0][lr]=w0.x; Bs[0][lh*8+1][lr]=w0.y; Bs[0][lh*8+2][lr]=w0.z; Bs[0][lh*8+3][lr]=w0.w;
        Bs[0][lh*8+4][lr]=w1.x; Bs[0][lh*8+5][lr]=w1.y; Bs[0][lh*8+6][lr]=w1.z; Bs[0][lh*8+7][lr]=w1.w;
    }
    __syncthreads();

    for (int k0 = 0; k0 < 512; k0 += 16) {
        int p = (k0 >> 4) & 1;
        float4 a0, a1, w0, w1;
        bool more = (k0 + 16 < 512);
        if (more) {
            a0 = *(const float4*)(Ap + k0 + 16);
            a1 = *(const float4*)(Ap + k0 + 20);
            w0 = *(const float4*)(Wp + k0 + 16);
            w1 = *(const float4*)(Wp + k0 + 20);
        }
#pragma unroll
        for (int kk = 0; kk < 16; kk++) {
            float a[8];
            *(float4*)&a[0] = *(const float4*)&As[p][kk][ty*8];
            *(float4*)&a[4] = *(const float4*)&As[p][kk][ty*8+4];
            float4 b0 = *(const float4*)&Bs[p][kk][tx*8];
            float4 b1 = *(const float4*)&Bs[p][kk][tx*8+4];
            float2 bp[4] = { make_float2(b0.x,b0.y), make_float2(b0.z,b0.w),
                             make_float2(b1.x,b1.y), make_float2(b1.z,b1.w) };
#pragma unroll
            for (int i = 0; i < 8; i++) {
                float2 ap = make_float2(a[i], a[i]);
#pragma unroll
                for (int j = 0; j < 4; j++) ffma2(acc[i][j], ap, bp[j]);
            }
        }
        if (more) {
            int q = p ^ 1;
            As[q][lh*8+0][lr]=a0.x; As[q][lh*8+1][lr]=a0.y; As[q][lh*8+2][lr]=a0.z; As[q][lh*8+3][lr]=a0.w;
            As[q][lh*8+4][lr]=a1.x; As[q][lh*8+5][lr]=a1.y; As[q][lh*8+6][lr]=a1.z; As[q][lh*8+7][lr]=a1.w;
            Bs[q][lh*8+0][lr]=w0.x; Bs[q][lh*8+1][lr]=w0.y; Bs[q][lh*8+2][lr]=w0.z; Bs[q][lh*8+3][lr]=w0.w;
            Bs[q][lh*8+4][lr]=w1.x; Bs[q][lh*8+5][lr]=w1.y; Bs[q][lh*8+6][lr]=w1.z; Bs[q][lh*8+7][lr]=w1.w;
        }
        __syncthreads();
    }

#pragma unroll
    for (int i = 0; i < 8; i++) {
        int m = m0 + ty*8 + i;
        int bb = m >> 10, t = m & 1023;
#pragma unroll
        for (int p = 0; p < 2; p++) {
            int n = n0 + tx*8 + p*4;
            int d = n >> 8, h = n & 255;
            float4 v;
            v.x = acc[i][p*2  ].x + bih[n  ] + bhh[n  ];
            v.y = acc[i][p*2  ].y + bih[n+1] + bhh[n+1];
            v.z = acc[i][p*2+1].x + bih[n+2] + bhh[n+2];
            v.w = acc[i][p*2+1].y + bih[n+3] + bhh[n+3];
            *(float4*)&g_xp[(((size_t)d*T_ + t)*B_ + bb)*H_ + h] = v;
        }
    }
}

// ---------------- 2) bidirectional RNN recurrence ----------------
// One CTA per (batch, dir). 512 threads. Thread tid: channel j=tid>>1,
// half=tid&1 covering h[half*128 : half*128+128). Partner reduce via shfl.
// Double-buffered h -> ONE barrier per step. smem weights as float4.
// (Proven best layout: broadcast h-LDS + single shfl reduce.)
__global__ __launch_bounds__(512, 1) void rnn_layer_kernel(
    const float* __restrict__ whh,     // [2][H][H] (this layer)
    int which_out)                     // 0 -> g_x1, 1 -> g_x2
{
    extern __shared__ float sm[];
    float4* Wt4  = (float4*)sm;                  // [WSH4][512] float4
    float*  hbuf = sm + WSH4 * 512 * 4;          // [2][HBUF]
    float*  xnext = which_out ? g_x2 : g_x1;

    int tid  = threadIdx.x;
    int j    = tid >> 1;          // output channel
    int half = tid & 1;           // which 128-slice of h
    int d = blockIdx.x & 1;
    int b = blockIdx.x >> 1;
    const float* Wd = whh + (size_t)d * H_ * H_;

    // register weights: W[j][half*128 + 2k], k=0..47
    float2 wreg2[WREG2];
    {
        const float2* wrow = (const float2*)(Wd + (size_t)j * H_ + half * 128);
#pragma unroll
        for (int k = 0; k < WREG2; k++) wreg2[k] = wrow[k];
    }
    // shared weights: Wt4[kk*512+tid] = W[j][half*128 + 96 + 4kk .. +3]
    for (int idx = tid; idx < WSH4 * 512; idx += 512) {
        int kk = idx >> 9;
        int t2 = idx & 511;
        int j2 = t2 >> 1, h2 = t2 & 1;
        Wt4[idx] = *(const float4*)(Wd + (size_t)j2 * H_ + h2 * 128 + 2*WREG2 + 4*kk);
    }
    for (int idx = tid; idx < 2 * HBUF; idx += 512) hbuf[idx] = 0.f;
    __syncthreads();

    const float* xpd = g_xp + (size_t)d * T_ * B_ * H_;
    float* outp = xnext + (size_t)b * T_ * 512 + d * H_ + j;

    int t = d ? (T_ - 1) : 0;
    int step = d ? -1 : 1;

    float xv  = xpd[((size_t)t * B_ + b) * H_ + j];
    float xnv = xpd[((size_t)(t + step) * B_ + b) * H_ + j];

    int rb = 0;
    for (int s = 0; s < T_; ++s) {
        float xfut = 0.f;
        if (s + 2 < T_)
            xfut = xpd[((size_t)(t + 2*step) * B_ + b) * H_ + j];  // 2-deep prefetch

        const float4* h4p = (const float4*)(hbuf + rb * HBUF + half * HSTRIDE);

        float2 a0 = make_float2(0.f,0.f), a1 = a0, a2 = a0, a3 = a0;
#pragma unroll
        for (int q = 0; q < WREG2/2; q++) {            // 24 float4 of h (reg W)
            float4 hv = h4p[q];
            ffma2((q & 1) ? a2 : a0, make_float2(hv.x, hv.y), wreg2[2*q]);
            ffma2((q & 1) ? a3 : a1, make_float2(hv.z, hv.w), wreg2[2*q+1]);
        }
#pragma unroll
        for (int q = 0; q < WSH4; q++) {               // 8 float4 of h (smem W)
            float4 hv = h4p[WREG2/2 + q];
            float4 w  = Wt4[q*512 + tid];
            ffma2((q & 1) ? a2 : a0, make_float2(hv.x, hv.y), make_float2(w.x, w.y));
            ffma2((q & 1) ? a3 : a1, make_float2(hv.z, hv.w), make_float2(w.z, w.w));
        }
        float ssum = (a0.x + a0.y) + (a1.x + a1.y)
                   + (a2.x + a2.y) + (a3.x + a3.y);
        float psum = __shfl_xor_sync(0xffffffffu, ssum, 1);
        float hn = ftanh(ssum + psum + xv);

        int wb = rb ^ 1;
        if (half == 0) hbuf[wb * HBUF + j + ((j >> 7) << 2)] = hn;  // padded pos
        else           outp[(size_t)t * 512] = hn;

        __syncthreads();                 // new h visible; old h reads all done
        xv = xnv; xnv = xfut;
        t += step;
        rb = wb;
    }
}

// ---------------- 3) head projections: relu(x2) @ [13x512]^T + biases ----------------
__global__ __launch_bounds__(256) void head_xp_kernel(
    const float* __restrict__ wi, const float* __restrict__ bi_ih, const float* __restrict__ bi_hh,
    const float* __restrict__ wf, const float* __restrict__ bf_ih, const float* __restrict__ bf_hh,
    const float* __restrict__ wc, const float* __restrict__ bc_ih, const float* __restrict__ bc_hh)
{
    __shared__ float Ws[13 * 512];
    __shared__ float bs[13];
    int tid = threadIdx.x;
    for (int idx = tid; idx < 13 * 512; idx += 256) {
        int n = idx / 512, k = idx % 512;
        float w;
        if (n < 3)      w = wi[n*512 + k];
        else if (n < 8) w = wf[(n-3)*512 + k];
        else            w = wc[(n-8)*512 + k];
        Ws[idx] = w;
    }
    if (tid < 13) {
        float bv;
        if (tid < 3)      bv = bi_ih[tid]   + bi_hh[tid];
        else if (tid < 8) bv = bf_ih[tid-3] + bf_hh[tid-3];
        else              bv = bc_ih[tid-8] + bc_hh[tid-8];
        bs[tid] = bv;
    }
    __syncthreads();

    int w = tid >> 5, lane = tid & 31;
    int m = blockIdx.x * 8 + w;
    const float* xr = g_x2 + (size_t)m * 512;

    float acc[13];
#pragma unroll
    for (int n = 0; n < 13; n++) acc[n] = 0.f;

    for (int i = 0; i < 16; i++) {
        int k = i * 32 + lane;
        float xv = xr[k];
        xv = xv > 0.f ? xv : 0.f;
#pragma unroll
        for (int n = 0; n < 13; n++) acc[n] += xv * Ws[n*512 + k];
    }
#pragma unroll
    for (int n = 0; n < 13; n++) {
#pragma unroll
        for (int off = 16; off; off >>= 1)
            acc[n] += __shfl_xor_sync(0xffffffff, acc[n], off);
    }
    if (lane == 0) {
        int bb = m >> 10, t = m & 1023;
        float* o = g_xph + ((size_t)t * B_ + bb) * 16;
#pragma unroll
        for (int n = 0; n < 13; n++) o[n] = acc[n] + bs[n];
    }
}

// ---------------- 4) head recurrences (3 tiny forward scans) ----------------
__global__ void head_rnn_kernel(
    const float* __restrict__ wi_hh,
    const float* __restrict__ wf_hh,
    const float* __restrict__ wc_hh,
    float* __restrict__ out)
{
    int hid = blockIdx.x % 3;
    int b   = blockIdx.x / 3;
    int lane = threadIdx.x;
    int C, off;
    size_t outoff;
    const float* Whh;
    if (hid == 0)      { C = 3; off = 0; outoff = 0;                         Whh = wi_hh; }
    else if (hid == 1) { C = 5; off = 3; outoff = (size_t)B_*T_*3;           Whh = wf_hh; }
    else               { C = 5; off = 8; outoff = (size_t)B_*T_*3 + (size_t)B_*T_*5; Whh = wc_hh; }

    float w[5] = {0,0,0,0,0};
    if (lane < C)
        for (int k = 0; k < C; k++) w[k] = Whh[lane*C + k];

    float h = 0.f;
    float* ob = out + outoff + (size_t)b * T_ * C;
    float xv = (lane < C) ? g_xph[((size_t)0 * B_ + b) * 16 + off + lane] : 0.f;
    for (int t = 0; t < T_; t++) {
        float xn = 0.f;
        if (t + 1 < T_ && lane < C)
            xn = g_xph[((size_t)(t+1) * B_ + b) * 16 + off + lane];
        float h0 = __shfl_sync(0xffffffff, h, 0);
        float h1 = __shfl_sync(0xffffffff, h, 1);
        float h2 = __shfl_sync(0xffffffff, h, 2);
        float h3 = __shfl_sync(0xffffffff, h, 3);
        float h4 = __shfl_sync(0xffffffff, h, 4);
        float acc = xv + h0*w[0] + h1*w[1] + h2*w[2] + h3*w[3] + h4*w[4];
        h = ftanh(acc);
        if (lane < C) ob[(size_t)t * C + lane] = h;
        xv = xn;
    }
}

// ---------------- launch ----------------
extern "C" void kernel_launch(void* const* d_in, const int* in_sizes, int n_in,
                              void* d_out, int out_size) {
    const int*   tokens = (const int*)  d_in[0];
    const float* emb    = (const float*)d_in[1];
    const float* w_ih   = (const float*)d_in[2];   // [2][2][256][512]
    const float* w_hh   = (const float*)d_in[3];   // [2][2][256][256]
    const float* b_ih   = (const float*)d_in[4];   // [2][2][256]
    const float* b_hh   = (const float*)d_in[5];
    const float* iw_ih  = (const float*)d_in[6];
    const float* iw_hh  = (const float*)d_in[7];
    const float* ib_ih  = (const float*)d_in[8];
    const float* ib_hh  = (const float*)d_in[9];
    const float* fw_ih  = (const float*)d_in[10];
    const float* fw_hh  = (const float*)d_in[11];
    const float* fb_ih  = (const float*)d_in[12];
    const float* fb_hh  = (const float*)d_in[13];
    const float* cw_ih  = (const float*)d_in[14];
    const float* cw_hh  = (const float*)d_in[15];
    const float* cb_ih  = (const float*)d_in[16];
    const float* cb_hh  = (const float*)d_in[17];
    float* out = (float*)d_out;

    const int rnn_smem = (WSH4 * 512 * 4 + 2 * HBUF) * 4;   // ~66 KB
    cudaFuncSetAttribute(rnn_layer_kernel,
                         cudaFuncAttributeMaxDynamicSharedMemorySize, rnn_smem);

    // layer 0: projection (fused embedding gather) + scan
    gemm_xp_kernel<<<dim3(M_/128, 512/128), 256>>>(0, tokens, emb,
                                                   w_ih, b_ih, b_hh);
    rnn_layer_kernel<<<B_ * 2, 512, rnn_smem>>>(w_hh, 0);

    // layer 1: projection + scan
    gemm_xp_kernel<<<dim3(M_/128, 512/128), 256>>>(1, tokens, emb,
                                                   w_ih + 2*H_*E_,
                                                   b_ih + 2*H_, b_hh + 2*H_);
    rnn_layer_kernel<<<B_ * 2, 512, rnn_smem>>>(w_hh + 2*H_*H_, 1);

    // head projections (with ReLU on the fly)
    head_xp_kernel<<<M_/8, 256>>>(iw_ih, ib_ih, ib_hh,
                                  fw_ih, fb_ih, fb_hh,
                                  cw_ih, cb_ih, cb_hh);

    // head scans -> final output
    head_rnn_kernel<<<B_ * 3, 32>>>(iw_hh, fw_hh, cw_hh, out);
}

// round 15
// speedup vs baseline: 1.3756x; 1.3060x over previous
#include <cuda_runtime.h>
#include <cuda_bf16.h>
#include <math.h>
#include <stdint.h>

#define B_ 64
#define T_ 1024
#define E_ 512
#define H_ 256
#define M_ (B_*T_)          // 65536

// RNN constants (proven best layout, ~1014us/launch)
#define WREG2 48
#define WSH4  8
#define HSTRIDE 132
#define HBUF   264

// ---------------- scratch (device globals; no allocation allowed) ----------------
__device__ float g_xp[(size_t)2*T_*B_*H_];     // per-layer projections [2][T][B][H]
__device__ float g_x1[(size_t)M_*512];         // layer0 output concat  [M,512]
__device__ float g_x2[(size_t)M_*512];         // layer1 output concat  [M,512]
__device__ float g_xph[(size_t)T_*B_*16];      // head projections      [T][B][16]
__device__ __nv_bfloat16 g_ah[(size_t)M_*512]; // x hi (bf16)
__device__ __nv_bfloat16 g_al[(size_t)M_*512]; // x lo (bf16 residual)
__device__ __nv_bfloat16 g_wh[(size_t)2*512*512]; // W hi per layer
__device__ __nv_bfloat16 g_wl[(size_t)2*512*512]; // W lo per layer

// ---------------- packed f32x2 FMA ----------------
__device__ __forceinline__ void ffma2(float2 &acc, float2 a, float2 b) {
    asm("fma.rn.f32x2 %0, %1, %2, %0;"
        : "+l"(reinterpret_cast<unsigned long long&>(acc))
        : "l"(reinterpret_cast<unsigned long long&>(a)),
          "l"(reinterpret_cast<unsigned long long&>(b)));
}

__device__ __forceinline__ float ftanh(float x) {
    float ax = fabsf(x);
    float e  = __expf(-2.f * ax);
    float r  = __fdividef(1.f - e, 1.f + e);
    return copysignf(r, x);
}

__device__ __forceinline__ uint32_t s2u(const void* p) {
    uint32_t a;
    asm("{ .reg .u64 t; cvta.to.shared.u64 t, %1; cvt.u32.u64 %0, t; }"
        : "=r"(a) : "l"(p));
    return a;
}
__device__ __forceinline__ void cp_async16(uint32_t smem, const void* gptr) {
    asm volatile("cp.async.cg.shared.global [%0], [%1], 16;"
                 :: "r"(smem), "l"(gptr) : "memory");
}
__device__ __forceinline__ void ldmatrix_x4(uint32_t* r, uint32_t addr) {
    asm volatile("ldmatrix.sync.aligned.m8n8.x4.shared.b16 {%0,%1,%2,%3}, [%4];"
                 : "=r"(r[0]), "=r"(r[1]), "=r"(r[2]), "=r"(r[3]) : "r"(addr));
}
__device__ __forceinline__ void mma16816(float* d, const uint32_t* a,
                                         uint32_t b0, uint32_t b1) {
    asm volatile("mma.sync.aligned.m16n8k16.row.col.f32.bf16.bf16.f32 "
                 "{%0,%1,%2,%3}, {%4,%5,%6,%7}, {%8,%9}, {%0,%1,%2,%3};"
                 : "+f"(d[0]), "+f"(d[1]), "+f"(d[2]), "+f"(d[3])
                 : "r"(a[0]), "r"(a[1]), "r"(a[2]), "r"(a[3]),
                   "r"(b0), "r"(b1));
}

// ---------------- 0a) convert W (both layers) fp32 -> bf16 hi/lo --------------
__global__ void conv_w_kernel(const float* __restrict__ w) {
    int idx = blockIdx.x * 256 + threadIdx.x;     // x4 elems; 2*512*512 total
    float4 v = *(const float4*)(w + (size_t)idx * 4);
    __nv_bfloat16 h0 = __float2bfloat16_rn(v.x), h1 = __float2bfloat16_rn(v.y);
    __nv_bfloat16 h2 = __float2bfloat16_rn(v.z), h3 = __float2bfloat16_rn(v.w);
    __nv_bfloat16 l0 = __float2bfloat16_rn(v.x - __bfloat162float(h0));
    __nv_bfloat16 l1 = __float2bfloat16_rn(v.y - __bfloat162float(h1));
    __nv_bfloat16 l2 = __float2bfloat16_rn(v.z - __bfloat162float(h2));
    __nv_bfloat16 l3 = __float2bfloat16_rn(v.w - __bfloat162float(h3));
    __nv_bfloat162 hp0 = __halves2bfloat162(h0, h1), hp1 = __halves2bfloat162(h2, h3);
    __nv_bfloat162 lp0 = __halves2bfloat162(l0, l1), lp1 = __halves2bfloat162(l2, l3);
    uint2 hu, lu;
    hu.x = *(unsigned*)&hp0; hu.y = *(unsigned*)&hp1;
    lu.x = *(unsigned*)&lp0; lu.y = *(unsigned*)&lp1;
    *(uint2*)(g_wh + (size_t)idx * 4) = hu;
    *(uint2*)(g_wl + (size_t)idx * 4) = lu;
}

// ---------------- 0b) convert x fp32 -> bf16 hi/lo (fused emb gather) ---------
__global__ void conv_x_kernel(int which, const int* __restrict__ tokens,
                              const float* __restrict__ emb) {
    int idx = blockIdx.x * 256 + threadIdx.x;     // float4 id; total M*128
    int m = idx >> 7, c4 = idx & 127;
    float4 v;
    if (which) {
        v = *((const float4*)(g_x1 + (size_t)m * 512) + c4);
    } else {
        int tok = __ldg(&tokens[m]);
        v = *((const float4*)(emb + (size_t)tok * 512) + c4);
    }
    __nv_bfloat16 h0 = __float2bfloat16_rn(v.x), h1 = __float2bfloat16_rn(v.y);
    __nv_bfloat16 h2 = __float2bfloat16_rn(v.z), h3 = __float2bfloat16_rn(v.w);
    __nv_bfloat16 l0 = __float2bfloat16_rn(v.x - __bfloat162float(h0));
    __nv_bfloat16 l1 = __float2bfloat16_rn(v.y - __bfloat162float(h1));
    __nv_bfloat16 l2 = __float2bfloat16_rn(v.z - __bfloat162float(h2));
    __nv_bfloat16 l3 = __float2bfloat16_rn(v.w - __bfloat162float(h3));
    __nv_bfloat162 hp0 = __halves2bfloat162(h0, h1), hp1 = __halves2bfloat162(h2, h3);
    __nv_bfloat162 lp0 = __halves2bfloat162(l0, l1), lp1 = __halves2bfloat162(l2, l3);
    uint2 hu, lu;
    hu.x = *(unsigned*)&hp0; hu.y = *(unsigned*)&hp1;
    lu.x = *(unsigned*)&lp0; lu.y = *(unsigned*)&lp1;
    *(uint2*)(g_ah + (size_t)m * 512 + c4 * 4) = hu;
    *(uint2*)(g_al + (size_t)m * 512 + c4 * 4) = lu;
}

// ---------------- 1) HMMA split-bf16 projection GEMM -------------------------
// CTA 256 thr / 8 warps; tile 128(m) x 128(n); k-chunks of 64 bf16 (128B rows,
// SW128 swizzle). 3 passes (Ah*Wh, Ah*Wl, Al*Wh) x 8 chunks, cp.async
// double-buffered. Warp tile 32x64 via m16n8k16 bf16 mma, fp32 accum.
__global__ __launch_bounds__(256, 2) void mma_gemm_kernel(
    int layer, const float* __restrict__ bih, const float* __restrict__ bhh)
{
    extern __shared__ __align__(128) char smem[];
    // layout: As0[16K] Bs0[16K] As1[16K] Bs1[16K] bias[512B]
    char* bufA[2] = { smem,            smem + 32768 };
    char* bufB[2] = { smem + 16384,    smem + 49152 };
    float* bias_s = (float*)(smem + 65536);

    int tid = threadIdx.x, wid = tid >> 5, l = tid & 31;
    int m0 = blockIdx.x * 128, n0 = blockIdx.y * 128;
    int wm = wid & 3, wn = wid >> 2;          // warp tile: m=wm*32, n=wn*64

    const __nv_bfloat16* whl = g_wh + (size_t)layer * 512 * 512;
    const __nv_bfloat16* wll = g_wl + (size_t)layer * 512 * 512;

    // bias into smem
    if (tid < 128) bias_s[tid] = bih[n0 + tid] + bhh[n0 + tid];

    // per-thread ldmatrix geometry
    int rowA0 = wm * 32 + ((l >> 3) & 1) * 8 + (l & 7);
    int rowB0 = wn * 64 + ((l >> 3) & 1) * 8 + (l & 7);
    int koff  = (l >> 4) * 16;                // 0 or 16 bytes
    int swx   = (l & 7) * 16;                 // SW128 xor term

    float d[2][8][4];
#pragma unroll
    for (int mi = 0; mi < 2; mi++)
#pragma unroll
        for (int nj = 0; nj < 8; nj++)
#pragma unroll
            for (int c = 0; c < 4; c++) d[mi][nj][c] = 0.f;

    // chunk source selector
    auto issue_load = [&](int ck, int p) {
        int pass = ck >> 3;
        int k0 = (ck & 7) * 64;
        const __nv_bfloat16* Asrc = (pass == 2) ? g_al : g_ah;
        const __nv_bfloat16* Bsrc = (pass == 1) ? wll : whl;
        uint32_t au = s2u(bufA[p]), bu = s2u(bufB[p]);
#pragma unroll
        for (int s = 0; s < 4; s++) {
            int lin = tid * 4 + s;            // 0..1023
            int row = lin >> 3, c = lin & 7;
            uint32_t soff = row * 128 + ((c * 16) ^ ((row & 7) * 16));
            cp_async16(au + soff, Asrc + (size_t)(m0 + row) * 512 + k0 + c * 8);
            cp_async16(bu + soff, Bsrc + (size_t)(n0 + row) * 512 + k0 + c * 8);
        }
        asm volatile("cp.async.commit_group;" ::: "memory");
    };

    issue_load(0, 0);
    asm volatile("cp.async.wait_group 0;" ::: "memory");
    __syncthreads();

    for (int ck = 0; ck < 24; ck++) {
        int p = ck & 1;
        if (ck + 1 < 24) issue_load(ck + 1, p ^ 1);

        uint32_t aBase = s2u(bufA[p]), bBase = s2u(bufB[p]);
#pragma unroll
        for (int q = 0; q < 4; q++) {         // 4 x k16 within the 64-chunk
            uint32_t low = (uint32_t)((q * 32 + koff) ^ swx);
            uint32_t afr[2][4];
#pragma unroll
            for (int mi = 0; mi < 2; mi++)
                ldmatrix_x4(afr[mi], aBase + (rowA0 + mi * 16) * 128 + low);
            uint32_t bfr[4][4];
#pragma unroll
            for (int ni = 0; ni < 4; ni++)
                ldmatrix_x4(bfr[ni], bBase + (rowB0 + ni * 16) * 128 + low);
#pragma unroll
            for (int mi = 0; mi < 2; mi++)
#pragma unroll
                for (int nj = 0; nj < 8; nj++)
                    mma16816(d[mi][nj], afr[mi],
                             bfr[nj >> 1][nj & 1], bfr[nj >> 1][2 + (nj & 1)]);
        }
        if (ck + 1 < 24) asm volatile("cp.async.wait_group 0;" ::: "memory");
        __syncthreads();
    }

    // epilogue: D fragment (m16n8): c0,c1 -> row l/4; c2,c3 -> row l/4+8
#pragma unroll
    for (int mi = 0; mi < 2; mi++) {
#pragma unroll
        for (int r2 = 0; r2 < 2; r2++) {
            int m = m0 + wm * 32 + mi * 16 + (l >> 2) + r2 * 8;
            int bb = m >> 10, t = m & 1023;
#pragma unroll
            for (int nj = 0; nj < 8; nj++) {
                int nloc = wn * 64 + nj * 8 + (l & 3) * 2;
                int n = n0 + nloc;
                int dd = n >> 8, h = n & 255;
                float2 v;
                v.x = d[mi][nj][r2 * 2    ] + bias_s[nloc    ];
                v.y = d[mi][nj][r2 * 2 + 1] + bias_s[nloc + 1];
                *(float2*)&g_xp[(((size_t)dd * T_ + t) * B_ + bb) * H_ + h] = v;
            }
        }
    }
}

// ---------------- 2) bidirectional RNN recurrence (proven best) --------------
__global__ __launch_bounds__(512, 1) void rnn_layer_kernel(
    const float* __restrict__ whh, int which_out)
{
    extern __shared__ float sm[];
    float4* Wt4  = (float4*)sm;                  // [WSH4][512] float4
    float*  hbuf = sm + WSH4 * 512 * 4;          // [2][HBUF]
    float*  xnext = which_out ? g_x2 : g_x1;

    int tid  = threadIdx.x;
    int j    = tid >> 1;
    int half = tid & 1;
    int d = blockIdx.x & 1;
    int b = blockIdx.x >> 1;
    const float* Wd = whh + (size_t)d * H_ * H_;

    float2 wreg2[WREG2];
    {
        const float2* wrow = (const float2*)(Wd + (size_t)j * H_ + half * 128);
#pragma unroll
        for (int k = 0; k < WREG2; k++) wreg2[k] = wrow[k];
    }
    for (int idx = tid; idx < WSH4 * 512; idx += 512) {
        int kk = idx >> 9;
        int t2 = idx & 511;
        int j2 = t2 >> 1, h2 = t2 & 1;
        Wt4[idx] = *(const float4*)(Wd + (size_t)j2 * H_ + h2 * 128 + 2*WREG2 + 4*kk);
    }
    for (int idx = tid; idx < 2 * HBUF; idx += 512) hbuf[idx] = 0.f;
    __syncthreads();

    const float* xpd = g_xp + (size_t)d * T_ * B_ * H_;
    float* outp = xnext + (size_t)b * T_ * 512 + d * H_ + j;

    int t = d ? (T_ - 1) : 0;
    int step = d ? -1 : 1;

    float xv  = xpd[((size_t)t * B_ + b) * H_ + j];
    float xnv = xpd[((size_t)(t + step) * B_ + b) * H_ + j];

    int rb = 0;
    for (int s = 0; s < T_; ++s) {
        float xfut = 0.f;
        if (s + 2 < T_)
            xfut = xpd[((size_t)(t + 2*step) * B_ + b) * H_ + j];

        const float4* h4p = (const float4*)(hbuf + rb * HBUF + half * HSTRIDE);

        float2 a0 = make_float2(0.f,0.f), a1 = a0, a2 = a0, a3 = a0;
#pragma unroll
        for (int q = 0; q < WREG2/2; q++) {
            float4 hv = h4p[q];
            ffma2((q & 1) ? a2 : a0, make_float2(hv.x, hv.y), wreg2[2*q]);
            ffma2((q & 1) ? a3 : a1, make_float2(hv.z, hv.w), wreg2[2*q+1]);
        }
#pragma unroll
        for (int q = 0; q < WSH4; q++) {
            float4 hv = h4p[WREG2/2 + q];
            float4 w  = Wt4[q*512 + tid];
            ffma2((q & 1) ? a2 : a0, make_float2(hv.x, hv.y), make_float2(w.x, w.y));
            ffma2((q & 1) ? a3 : a1, make_float2(hv.z, hv.w), make_float2(w.z, w.w));
        }
        float ssum = (a0.x + a0.y) + (a1.x + a1.y)
                   + (a2.x + a2.y) + (a3.x + a3.y);
        float psum = __shfl_xor_sync(0xffffffffu, ssum, 1);
        float hn = ftanh(ssum + psum + xv);

        int wb = rb ^ 1;
        if (half == 0) hbuf[wb * HBUF + j + ((j >> 7) << 2)] = hn;
        else           outp[(size_t)t * 512] = hn;

        __syncthreads();
        xv = xnv; xnv = xfut;
        t += step;
        rb = wb;
    }
}

// ---------------- 3) head projections ----------------
__global__ __launch_bounds__(256) void head_xp_kernel(
    const float* __restrict__ wi, const float* __restrict__ bi_ih, const float* __restrict__ bi_hh,
    const float* __restrict__ wf, const float* __restrict__ bf_ih, const float* __restrict__ bf_hh,
    const float* __restrict__ wc, const float* __restrict__ bc_ih, const float* __restrict__ bc_hh)
{
    __shared__ float Ws[13 * 512];
    __shared__ float bs[13];
    int tid = threadIdx.x;
    for (int idx = tid; idx < 13 * 512; idx += 256) {
        int n = idx / 512, k = idx % 512;
        float w;
        if (n < 3)      w = wi[n*512 + k];
        else if (n < 8) w = wf[(n-3)*512 + k];
        else            w = wc[(n-8)*512 + k];
        Ws[idx] = w;
    }
    if (tid < 13) {
        float bv;
        if (tid < 3)      bv = bi_ih[tid]   + bi_hh[tid];
        else if (tid < 8) bv = bf_ih[tid-3] + bf_hh[tid-3];
        else              bv = bc_ih[tid-8] + bc_hh[tid-8];
        bs[tid] = bv;
    }
    __syncthreads();

    int w = tid >> 5, lane = tid & 31;
    int m = blockIdx.x * 8 + w;
    const float* xr = g_x2 + (size_t)m * 512;

    float acc[13];
#pragma unroll
    for (int n = 0; n < 13; n++) acc[n] = 0.f;

    for (int i = 0; i < 16; i++) {
        int k = i * 32 + lane;
        float xv = xr[k];
        xv = xv > 0.f ? xv : 0.f;
#pragma unroll
        for (int n = 0; n < 13; n++) acc[n] += xv * Ws[n*512 + k];
    }
#pragma unroll
    for (int n = 0; n < 13; n++) {
#pragma unroll
        for (int off = 16; off; off >>= 1)
            acc[n] += __shfl_xor_sync(0xffffffff, acc[n], off);
    }
    if (lane == 0) {
        int bb = m >> 10, t = m & 1023;
        float* o = g_xph + ((size_t)t * B_ + bb) * 16;
#pragma unroll
        for (int n = 0; n < 13; n++) o[n] = acc[n] + bs[n];
    }
}

// ---------------- 4) head recurrences ----------------
__global__ void head_rnn_kernel(
    const float* __restrict__ wi_hh,
    const float* __restrict__ wf_hh,
    const float* __restrict__ wc_hh,
    float* __restrict__ out)
{
    int hid = blockIdx.x % 3;
    int b   = blockIdx.x / 3;
    int lane = threadIdx.x;
    int C, off;
    size_t outoff;
    const float* Whh;
    if (hid == 0)      { C = 3; off = 0; outoff = 0;                         Whh = wi_hh; }
    else if (hid == 1) { C = 5; off = 3; outoff = (size_t)B_*T_*3;           Whh = wf_hh; }
    else               { C = 5; off = 8; outoff = (size_t)B_*T_*3 + (size_t)B_*T_*5; Whh = wc_hh; }

    float w[5] = {0,0,0,0,0};
    if (lane < C)
        for (int k = 0; k < C; k++) w[k] = Whh[lane*C + k];

    float h = 0.f;
    float* ob = out + outoff + (size_t)b * T_ * C;
    float xv = (lane < C) ? g_xph[((size_t)0 * B_ + b) * 16 + off + lane] : 0.f;
    for (int t = 0; t < T_; t++) {
        float xn = 0.f;
        if (t + 1 < T_ && lane < C)
            xn = g_xph[((size_t)(t+1) * B_ + b) * 16 + off + lane];
        float h0 = __shfl_sync(0xffffffff, h, 0);
        float h1 = __shfl_sync(0xffffffff, h, 1);
        float h2 = __shfl_sync(0xffffffff, h, 2);
        float h3 = __shfl_sync(0xffffffff, h, 3);
        float h4 = __shfl_sync(0xffffffff, h, 4);
        float acc = xv + h0*w[0] + h1*w[1] + h2*w[2] + h3*w[3] + h4*w[4];
        h = ftanh(acc);
        if (lane < C) ob[(size_t)t * C + lane] = h;
        xv = xn;
    }
}

// ---------------- launch ----------------
extern "C" void kernel_launch(void* const* d_in, const int* in_sizes, int n_in,
                              void* d_out, int out_size) {
    const int*   tokens = (const int*)  d_in[0];
    const float* emb    = (const float*)d_in[1];
    const float* w_ih   = (const float*)d_in[2];   // [2][2][256][512]
    const float* w_hh   = (const float*)d_in[3];   // [2][2][256][256]
    const float* b_ih   = (const float*)d_in[4];   // [2][2][256]
    const float* b_hh   = (const float*)d_in[5];
    const float* iw_ih  = (const float*)d_in[6];
    const float* iw_hh  = (const float*)d_in[7];
    const float* ib_ih  = (const float*)d_in[8];
    const float* ib_hh  = (const float*)d_in[9];
    const float* fw_ih  = (const float*)d_in[10];
    const float* fw_hh  = (const float*)d_in[11];
    const float* fb_ih  = (const float*)d_in[12];
    const float* fb_hh  = (const float*)d_in[13];
    const float* cw_ih  = (const float*)d_in[14];
    const float* cw_hh  = (const float*)d_in[15];
    const float* cb_ih  = (const float*)d_in[16];
    const float* cb_hh  = (const float*)d_in[17];
    float* out = (float*)d_out;

    const int rnn_smem = (WSH4 * 512 * 4 + 2 * HBUF) * 4;
    cudaFuncSetAttribute(rnn_layer_kernel,
                         cudaFuncAttributeMaxDynamicSharedMemorySize, rnn_smem);
    const int mma_smem = 65536 + 512;
    cudaFuncSetAttribute(mma_gemm_kernel,
                         cudaFuncAttributeMaxDynamicSharedMemorySize, mma_smem);

    // convert weights once (both layers)
    conv_w_kernel<<<(2*512*512/4)/256, 256>>>(w_ih);

    // layer 0: gather+split x, HMMA GEMM, scan
    conv_x_kernel<<<(M_*128)/256, 256>>>(0, tokens, emb);
    mma_gemm_kernel<<<dim3(M_/128, 4), 256, mma_smem>>>(0, b_ih, b_hh);
    rnn_layer_kernel<<<B_ * 2, 512, rnn_smem>>>(w_hh, 0);

    // layer 1
    conv_x_kernel<<<(M_*128)/256, 256>>>(1, tokens, emb);
    mma_gemm_kernel<<<dim3(M_/128, 4), 256, mma_smem>>>(1, b_ih + 2*H_, b_hh + 2*H_);
    rnn_layer_kernel<<<B_ * 2, 512, rnn_smem>>>(w_hh + 2*H_*H_, 1);

    // heads
    head_xp_kernel<<<M_/8, 256>>>(iw_ih, ib_ih, ib_hh,
                                  fw_ih, fb_ih, fb_hh,
                                  cw_ih, cb_ih, cb_hh);
    head_rnn_kernel<<<B_ * 3, 32>>>(iw_hh, fw_hh, cw_hh, out);
}